// round 5
// baseline (speedup 1.0000x reference)
#include <cuda_runtime.h>

// DeepArcNet v3: block-GEMM formulation. Block = 16 samples = 96 token-columns.
// Activations live in shared as [e][96]; every linear layer is a register-tiled
// GEMM (6 rows x 6 token-pairs per thread, f32x2) with transposed weights staged
// in shared. Attention/softmax/LayerNorm are thread-per-token column ops.

#define TPB 96
#define SPB 16

typedef unsigned long long ull;

// shared layout (float offsets)
#define HSH 0                        // [68][96] activations H
#define QB  (68 * 96)                // [68][96] gemm buffer A
#define KB  (2 * 68 * 96)            // [68][96] gemm buffer B
#define WT  (3 * 68 * 96)            // [68*72]  staged (transposed) weights
#define SSH (3 * 68 * 96 + 68 * 72)  // [12][96] softmax probs / fc reduce
#define POSO (SSH + 12 * 96)         // [68] pos table
#define SM_FLOATS (POSO + 68)        // 25700 floats = 102800 B

__device__ __forceinline__ ull pk2(float x, float y) {
  ull r; asm("mov.b64 %0, {%1,%2};" : "=l"(r) : "f"(x), "f"(y)); return r;
}
__device__ __forceinline__ void upk2(ull a, float& x, float& y) {
  asm("mov.b64 {%0,%1}, %2;" : "=f"(x), "=f"(y) : "l"(a));
}
__device__ __forceinline__ ull ffma2(ull a, ull b, ull c) {
  ull d; asm("fma.rn.f32x2 %0, %1, %2, %3;" : "=l"(d) : "l"(a), "l"(b), "l"(c)); return d;
}

// stage W[NR][K] (global, row-major) -> wt[e][72] transposed in shared
__device__ __forceinline__ void stageT(float* dst, const float* __restrict__ src,
                                       int NR, int K, int tid) {
  int n = NR * K;
#pragma unroll 1
  for (int idx = tid; idx < n; idx += TPB) {
    int d = idx / K, e = idx - d * K;
    dst[e * 72 + d] = src[idx];
  }
}

// register-tiled GEMM: dst[d][96] = wt[e][72]^T(d) * hsrc[e][96], d<NR, e<K
// thread tile: 6 output rows x 6 token-pairs (f32x2)
__device__ __forceinline__ void gemm(const float* wt, const float* hsrc,
                                     float* dst, int K, int NR,
                                     const float* __restrict__ bias, bool relu,
                                     int tr, int tc) {
  ull acc[36];
#pragma unroll
  for (int i = 0; i < 36; i++) acc[i] = 0ull;
  const float* wp = wt + tr * 6;
  const ull* hp = reinterpret_cast<const ull*>(hsrc) + tc * 6;
#pragma unroll 2
  for (int e = 0; e < K; e++) {
    ull wv[6], hv[6];
#pragma unroll
    for (int r = 0; r < 6; r++) { float w = wp[e * 72 + r]; wv[r] = pk2(w, w); }
#pragma unroll
    for (int c = 0; c < 6; c++) hv[c] = hp[e * 48 + c];
#pragma unroll
    for (int r = 0; r < 6; r++)
#pragma unroll
      for (int c = 0; c < 6; c++)
        acc[r * 6 + c] = ffma2(wv[r], hv[c], acc[r * 6 + c]);
  }
#pragma unroll
  for (int r = 0; r < 6; r++) {
    int d = tr * 6 + r;
    if (d < NR) {
      float bv = bias ? __ldg(bias + d) : 0.f;
      ull* drow = reinterpret_cast<ull*>(dst + d * 96) + tc * 6;
#pragma unroll
      for (int c = 0; c < 6; c++) {
        float fx, fy; upk2(acc[r * 6 + c], fx, fy);
        fx += bv; fy += bv;
        if (relu) { fx = fmaxf(fx, 0.f); fy = fmaxf(fy, 0.f); }
        drow[c] = pk2(fx, fy);
      }
    }
  }
}

__device__ __forceinline__ void ln68(float* h, const float* __restrict__ g,
                                     const float* __restrict__ b) {
  float m = 0.f;
#pragma unroll
  for (int i = 0; i < 68; i++) m += h[i];
  m *= (1.0f / 68.0f);
  float v = 0.f;
#pragma unroll
  for (int i = 0; i < 68; i++) { float d = h[i] - m; v = fmaf(d, d, v); }
  v *= (1.0f / 68.0f);
  float r = rsqrtf(v + 1e-5f);
#pragma unroll
  for (int i = 0; i < 68; i++)
    h[i] = fmaf((h[i] - m) * r, __ldg(g + i), __ldg(b + i));
}

__global__ void __launch_bounds__(TPB) dan_kernel(
    const float* __restrict__ x,     const float* __restrict__ convw,
    const float* __restrict__ convb, const float* __restrict__ lembw,
    const float* __restrict__ lembb, const float* __restrict__ wq,
    const float* __restrict__ wk,    const float* __restrict__ wv,
    const float* __restrict__ projw, const float* __restrict__ projb,
    const float* __restrict__ ff1w,  const float* __restrict__ ff1b,
    const float* __restrict__ ff2w,  const float* __restrict__ ff2b,
    const float* __restrict__ ln1g,  const float* __restrict__ ln1b,
    const float* __restrict__ ln2g,  const float* __restrict__ ln2b,
    const float* __restrict__ lnfg,  const float* __restrict__ lnfb,
    const float* __restrict__ fcw,   const float* __restrict__ fcb,
    float* __restrict__ out)
{
  extern __shared__ float smf[];
  const int tid = threadIdx.x;
  const int samp0 = blockIdx.x * SPB;
  const int j = tid;                 // token column 0..95
  const int s = j / 6, t = j - s * 6;
  const int sb = s * 6;              // sample column base
  const int tr = tid / 8, tc = tid % 8;  // gemm tile coords

  // pos table: pos[t][j4] = [sin(t), sin(t/18), cos(t), cos(t/18)]
  if (tid < 68) {
    int tt = tid >> 2, j4 = tid & 3;
    float ang = (j4 & 1) ? ((float)tt * (1.0f / 18.0f)) : (float)tt;
    smf[POSO + tid] = (j4 < 2) ? sinf(ang) : cosf(ang);
  }

  // depthwise conv 5x5 stride(2,2) + embed -> H column j (channel = t)
  {
    float lw[4], lb[4];
#pragma unroll
    for (int q = 0; q < 4; q++) { lw[q] = __ldg(lembw + t * 4 + q); lb[q] = __ldg(lembb + t * 4 + q); }
    float cb = __ldg(convb + t);
    const float* xp0 = x + ((size_t)(samp0 + s) * 6 + t) * 185;
    float h0[68];
#pragma unroll 1
    for (int tt = 0; tt < 17; tt++) {
      const float* xp = xp0 + tt * 10;
      float acc = 0.f;
#pragma unroll
      for (int i = 0; i < 25; i++) acc = fmaf(__ldg(xp + i), __ldg(convw + t * 25 + i), acc);
      float xc = fmaxf(acc + cb, 0.f);
#pragma unroll
      for (int q = 0; q < 4; q++) h0[tt * 4 + q] = fmaf(xc, lw[q], lb[q]);
    }
    __syncthreads();  // pos ready
#pragma unroll 1
    for (int e = 0; e < 68; e++)
      smf[HSH + e * 96 + j] = h0[e] + smf[POSO + ((e >> 2) << 2) + (e & 3)];
  }

#pragma unroll 1
  for (int l = 0; l < 2; l++) {
    // ---- Q = Wq * H -> qb ----
    __syncthreads();
    stageT(smf + WT, wq + l * 4624, 68, 68, tid);
    __syncthreads();
    gemm(smf + WT, smf + HSH, smf + QB, 68, 68, nullptr, false, tr, tc);

    // ---- K = Wk * H -> kb ----
    __syncthreads();
    stageT(smf + WT, wk + l * 4624, 68, 68, tid);
    __syncthreads();
    gemm(smf + WT, smf + HSH, smf + KB, 68, 68, nullptr, false, tr, tc);
    __syncthreads();

    // ---- scores + softmax (both heads), thread-per-token ----
    {
      float qv[68];
#pragma unroll 1
      for (int d = 0; d < 68; d++) qv[d] = smf[QB + d * 96 + j];
#pragma unroll 1
      for (int hh = 0; hh < 2; hh++) {
        float sc[6];
#pragma unroll 1
        for (int t2 = 0; t2 < 6; t2++) {
          float acc = 0.f;
#pragma unroll
          for (int dd = 0; dd < 34; dd++)
            acc = fmaf(qv[hh * 34 + dd], smf[KB + (hh * 34 + dd) * 96 + sb + t2], acc);
          sc[t2] = acc * 0.17149858514f;  // 34^-0.5
        }
        float mx = sc[0];
#pragma unroll
        for (int t2 = 1; t2 < 6; t2++) mx = fmaxf(mx, sc[t2]);
        float ssum = 0.f;
#pragma unroll
        for (int t2 = 0; t2 < 6; t2++) { sc[t2] = __expf(sc[t2] - mx); ssum += sc[t2]; }
        float inv = 1.0f / ssum;
#pragma unroll
        for (int t2 = 0; t2 < 6; t2++)
          smf[SSH + (hh * 6 + t2) * 96 + j] = sc[t2] * inv;
      }
    }

    // ---- V = Wv * H -> qb (overwrites Q, already consumed) ----
    __syncthreads();
    stageT(smf + WT, wv + l * 4624, 68, 68, tid);
    __syncthreads();
    gemm(smf + WT, smf + HSH, smf + QB, 68, 68, nullptr, false, tr, tc);
    __syncthreads();

    // ---- A = softmax * V -> kb (overwrites K), thread-per-token ----
    {
      float p[12];
#pragma unroll
      for (int i = 0; i < 12; i++) p[i] = smf[SSH + i * 96 + j];
#pragma unroll 1
      for (int hh = 0; hh < 2; hh++) {
#pragma unroll 1
        for (int dd = 0; dd < 34; dd++) {
          int row = hh * 34 + dd;
          float acc = 0.f;
#pragma unroll
          for (int t2 = 0; t2 < 6; t2++)
            acc = fmaf(p[hh * 6 + t2], smf[QB + row * 96 + sb + t2], acc);
          smf[KB + row * 96 + j] = acc;
        }
      }
    }

    // ---- P = proj * A + b -> qb ----
    __syncthreads();
    stageT(smf + WT, projw + l * 4624, 68, 68, tid);
    __syncthreads();
    gemm(smf + WT, smf + KB, smf + QB, 68, 68, projb + l * 68, false, tr, tc);
    __syncthreads();

    // ---- LN1: H = LN(H + P) ----
    {
      float h[68];
#pragma unroll 1
      for (int e = 0; e < 68; e++) h[e] = smf[HSH + e * 96 + j] + smf[QB + e * 96 + j];
      ln68(h, ln1g + l * 68, ln1b + l * 68);
#pragma unroll 1
      for (int e = 0; e < 68; e++) smf[HSH + e * 96 + j] = h[e];
    }

    // ---- F = relu(ff1 * H + b) -> qb (34 rows) ----
    __syncthreads();
    stageT(smf + WT, ff1w + l * 2312, 34, 68, tid);
    __syncthreads();
    gemm(smf + WT, smf + HSH, smf + QB, 68, 34, ff1b + l * 34, true, tr, tc);

    // ---- G = ff2 * F + b -> kb ----
    __syncthreads();
    stageT(smf + WT, ff2w + l * 2312, 68, 34, tid);
    __syncthreads();
    gemm(smf + WT, smf + QB, smf + KB, 34, 68, ff2b + l * 68, false, tr, tc);
    __syncthreads();

    // ---- LN2 (+ final LN on last layer): H = LN(H + G) ----
    {
      float h[68];
#pragma unroll 1
      for (int e = 0; e < 68; e++) h[e] = smf[HSH + e * 96 + j] + smf[KB + e * 96 + j];
      ln68(h, ln2g + l * 68, ln2b + l * 68);
      if (l == 1) ln68(h, lnfg, lnfb);
#pragma unroll 1
      for (int e = 0; e < 68; e++) smf[HSH + e * 96 + j] = h[e];
    }
  }

  // ---- final FC [6 x 408] over flattened (tok, e) ----
  __syncthreads();
#pragma unroll 1
  for (int idx = tid; idx < 2448; idx += TPB) smf[WT + idx] = fcw[idx];
  __syncthreads();
  {
    ull hq[34];
#pragma unroll 1
    for (int i = 0; i < 34; i++)
      hq[i] = pk2(smf[HSH + (2 * i) * 96 + j], smf[HSH + (2 * i + 1) * 96 + j]);
#pragma unroll 1
    for (int o = 0; o < 6; o++) {
      const ull* wp = reinterpret_cast<const ull*>(smf + WT + o * 408 + t * 68);
      ull a0 = 0ull, a1 = 0ull;
#pragma unroll
      for (int i = 0; i < 34; i += 2) {
        a0 = ffma2(wp[i], hq[i], a0);
        a1 = ffma2(wp[i + 1], hq[i + 1], a1);
      }
      float x0, y0, x1, y1; upk2(a0, x0, y0); upk2(a1, x1, y1);
      smf[SSH + j * 6 + o] = (x0 + y0) + (x1 + y1);
    }
  }
  __syncthreads();
  if (t == 0) {
#pragma unroll 1
    for (int o = 0; o < 6; o++) {
      float v = __ldg(fcb + o);
#pragma unroll
      for (int tt = 0; tt < 6; tt++) v += smf[SSH + (sb + tt) * 6 + o];
      out[(size_t)(samp0 + s) * 6 + o] = fmaxf(v, 0.f);
    }
  }
}

extern "C" void kernel_launch(void* const* d_in, const int* in_sizes, int n_in,
                              void* d_out, int out_size) {
  const float* x     = (const float*)d_in[0];
  const float* convw = (const float*)d_in[1];
  const float* convb = (const float*)d_in[2];
  const float* lembw = (const float*)d_in[3];
  const float* lembb = (const float*)d_in[4];
  const float* wq    = (const float*)d_in[5];
  const float* wk    = (const float*)d_in[6];
  const float* wv    = (const float*)d_in[7];
  const float* projw = (const float*)d_in[8];
  const float* projb = (const float*)d_in[9];
  const float* ff1w  = (const float*)d_in[10];
  const float* ff1b  = (const float*)d_in[11];
  const float* ff2w  = (const float*)d_in[12];
  const float* ff2b  = (const float*)d_in[13];
  const float* ln1g  = (const float*)d_in[14];
  const float* ln1b  = (const float*)d_in[15];
  const float* ln2g  = (const float*)d_in[16];
  const float* ln2b  = (const float*)d_in[17];
  const float* lnfg  = (const float*)d_in[18];
  const float* lnfb  = (const float*)d_in[19];
  const float* fcw   = (const float*)d_in[20];
  const float* fcb   = (const float*)d_in[21];
  float* out = (float*)d_out;

  int B = in_sizes[0] / (6 * 37 * 5);   // 32768
  int grid = B / SPB;                   // 2048
  int smem = SM_FLOATS * 4;             // 102800 B

  static int configured = 0;
  if (!configured) {
    cudaFuncSetAttribute(dan_kernel, cudaFuncAttributeMaxDynamicSharedMemorySize, smem);
    configured = 1;
  }
  dan_kernel<<<grid, TPB, smem>>>(
      x, convw, convb, lembw, lembb, wq, wk, wv, projw, projb,
      ff1w, ff1b, ff2w, ff2b, ln1g, ln1b, ln2g, ln2b, lnfg, lnfb,
      fcw, fcb, out);
}

// round 8
// speedup vs baseline: 2.2738x; 2.2738x over previous
#include <cuda_runtime.h>

// DeepArcNet v4.1: block GEMM, 16 samples (96 token-columns) per block, TPB=192.
// Weights staged transposed + row-pair packed (ull) in shared: GEMM weight loads
// are whole-warp-uniform LDS.64 (broadcast), activation loads per-lane scalar
// (conflict-free). Thread tile = 6 row-pairs x 3 columns (18 FFMA2/k-step).
// (v4 bug fix: SPB was 32 while the datapath covers 16 samples.)

#define TPB 192
#define SPB 16

typedef unsigned long long ull;

// float-offset layout in dynamic shared (101,040 B total)
#define WT2_U 0                    // ull wt2[68*37] = 20128 B; aliased as float[2448] for fc
#define H_F   5032                 // H  [68][96]
#define A_F   (H_F + 6528)         // Abuf [68][96]  (aliased: conv scratch xc[16][6][17])
#define B_F   (A_F + 6528)         // Bbuf [68][96]
#define POS_F (B_F + 6528)         // pos[68]
#define RED_F (POS_F + 68)         // red[16][36]
#define SM_FLOATS (RED_F + 576)

__device__ __forceinline__ ull pk2(float x, float y) {
  ull r; asm("mov.b64 %0, {%1,%2};" : "=l"(r) : "f"(x), "f"(y)); return r;
}
__device__ __forceinline__ void upk2(ull a, float& x, float& y) {
  asm("mov.b64 {%0,%1}, %2;" : "=f"(x), "=f"(y) : "l"(a));
}
__device__ __forceinline__ ull ffma2(ull a, ull b, ull c) {
  ull d; asm("fma.rn.f32x2 %0, %1, %2, %3;" : "=l"(d) : "l"(a), "l"(b), "l"(c)); return d;
}

// stage W[NR][K] (row-major global) -> wt2[e][p] = (W[2p][e], W[2p+1][e]), NR even
__device__ __forceinline__ void stageT2(ull* wt2, const float* __restrict__ src,
                                        int NR, int K, int tid) {
  int NP = NR >> 1;
  int n = K * NP;
#pragma unroll 1
  for (int idx = tid; idx < n; idx += TPB) {
    int e = idx % K, p = idx / K;
    wt2[e * 37 + p] = pk2(__ldg(src + (2 * p) * K + e), __ldg(src + (2 * p + 1) * K + e));
  }
}

// dst[d][96] = sum_e W[d][e] * hsrc[e][96]  (+bias, opt relu)
// wt2: row-pair packed. tr = tid/32 (6 groups of 12 rows), col0 = (tid%32)*3
__device__ __forceinline__ void gemm(const ull* wt2, const float* hsrc, float* dst,
                                     int K, int NR, const float* __restrict__ bias,
                                     bool relu, int tr, int col0) {
  ull acc[18];
#pragma unroll
  for (int i = 0; i < 18; i++) acc[i] = 0ull;
  const ull* wp = wt2 + tr * 6;
  const float* hp = hsrc + col0;
#pragma unroll 2
  for (int e = 0; e < K; e++) {
    ull wv[6];
#pragma unroll
    for (int rp = 0; rp < 6; rp++) wv[rp] = wp[e * 37 + rp];
    ull hv[3];
#pragma unroll
    for (int cc = 0; cc < 3; cc++) { float h = hp[e * 96 + cc]; hv[cc] = pk2(h, h); }
#pragma unroll
    for (int rp = 0; rp < 6; rp++)
#pragma unroll
      for (int cc = 0; cc < 3; cc++)
        acc[rp * 3 + cc] = ffma2(wv[rp], hv[cc], acc[rp * 3 + cc]);
  }
#pragma unroll
  for (int rp = 0; rp < 6; rp++) {
    int d0 = tr * 12 + rp * 2;
    if (d0 < NR) {
      float b0 = bias ? __ldg(bias + d0) : 0.f;
      float b1 = bias ? __ldg(bias + d0 + 1) : 0.f;
#pragma unroll
      for (int cc = 0; cc < 3; cc++) {
        float f0, f1; upk2(acc[rp * 3 + cc], f0, f1);
        f0 += b0; f1 += b1;
        if (relu) { f0 = fmaxf(f0, 0.f); f1 = fmaxf(f1, 0.f); }
        dst[d0 * 96 + col0 + cc] = f0;
        dst[(d0 + 1) * 96 + col0 + cc] = f1;
      }
    }
  }
}

__global__ void __launch_bounds__(TPB) dan_kernel(
    const float* __restrict__ x,     const float* __restrict__ convw,
    const float* __restrict__ convb, const float* __restrict__ lembw,
    const float* __restrict__ lembb, const float* __restrict__ wq,
    const float* __restrict__ wk,    const float* __restrict__ wv,
    const float* __restrict__ projw, const float* __restrict__ projb,
    const float* __restrict__ ff1w,  const float* __restrict__ ff1b,
    const float* __restrict__ ff2w,  const float* __restrict__ ff2b,
    const float* __restrict__ ln1g,  const float* __restrict__ ln1b,
    const float* __restrict__ ln2g,  const float* __restrict__ ln2b,
    const float* __restrict__ lnfg,  const float* __restrict__ lnfb,
    const float* __restrict__ fcw,   const float* __restrict__ fcb,
    float* __restrict__ out)
{
  extern __shared__ float smf[];
  ull* wt2 = reinterpret_cast<ull*>(smf);     // WT2_U = 0
  float* Hs = smf + H_F;
  float* As = smf + A_F;
  float* Bs = smf + B_F;
  const int tid = threadIdx.x;
  const int samp0 = blockIdx.x * SPB;
  const int tr = tid >> 5, col0 = (tid & 31) * 3;    // gemm tile coords
  const int hd = tid / 96, c = tid - hd * 96;        // attention coords (head, column)
  const int s = c / 6, t = c - s * 6;                // column -> (sample, token)

  // pos table
  if (tid < 68) {
    int tt = tid >> 2, j4 = tid & 3;
    float ang = (j4 & 1) ? ((float)tt * (1.0f / 18.0f)) : (float)tt;
    smf[POS_F + tid] = (j4 < 2) ? sinf(ang) : cosf(ang);
  }

  // depthwise conv 5x5 stride(2,2) -> xc (aliases Abuf): 16*102 = 1632 outputs
#pragma unroll 1
  for (int o = tid; o < SPB * 102; o += TPB) {
    int ss = o / 102, r = o % 102, ch = r / 17, tt = r % 17;
    const float* xp = x + ((size_t)(samp0 + ss) * 6 + ch) * 185 + tt * 10;
    float acc = 0.f;
#pragma unroll
    for (int i = 0; i < 25; i++) acc = fmaf(__ldg(xp + i), __ldg(convw + ch * 25 + i), acc);
    As[ss * 102 + ch * 17 + tt] = fmaxf(acc + __ldg(convb + ch), 0.f);
  }
  __syncthreads();

  // embed -> H[e][c]
  if (tid < 96) {
    float lw[4], lb[4];
#pragma unroll
    for (int q4 = 0; q4 < 4; q4++) {
      lw[q4] = __ldg(lembw + t * 4 + q4);
      lb[q4] = __ldg(lembb + t * 4 + q4);
    }
#pragma unroll 1
    for (int tt = 0; tt < 17; tt++) {
      float xv = As[s * 102 + t * 17 + tt];
#pragma unroll
      for (int q4 = 0; q4 < 4; q4++) {
        int e = tt * 4 + q4;
        Hs[e * 96 + c] = fmaf(xv, lw[q4], lb[q4]) + smf[POS_F + e];
      }
    }
  }

  float p[6];  // softmax probs, live across V-gemm

#pragma unroll 1
  for (int l = 0; l < 2; l++) {
    // Q = Wq*H -> A
    __syncthreads();
    stageT2(wt2, wq + l * 4624, 68, 68, tid);
    __syncthreads();
    gemm(wt2, Hs, As, 68, 68, nullptr, false, tr, col0);
    // K = Wk*H -> B
    __syncthreads();
    stageT2(wt2, wk + l * 4624, 68, 68, tid);
    __syncthreads();
    gemm(wt2, Hs, Bs, 68, 68, nullptr, false, tr, col0);
    __syncthreads();

    // scores + softmax per (c, head); also stage Wv (WT free)
    {
      float qv[34];
#pragma unroll 1
      for (int d = 0; d < 34; d++) qv[d] = As[(hd * 34 + d) * 96 + c];
      float sc[6];
#pragma unroll 1
      for (int t2 = 0; t2 < 6; t2++) {
        float acc = 0.f;
#pragma unroll
        for (int d = 0; d < 34; d++)
          acc = fmaf(qv[d], Bs[(hd * 34 + d) * 96 + s * 6 + t2], acc);
        sc[t2] = acc * 0.17149858514f;  // 34^-0.5
      }
      float mx = sc[0];
#pragma unroll
      for (int t2 = 1; t2 < 6; t2++) mx = fmaxf(mx, sc[t2]);
      float ssum = 0.f;
#pragma unroll
      for (int t2 = 0; t2 < 6; t2++) { sc[t2] = __expf(sc[t2] - mx); ssum += sc[t2]; }
      float inv = 1.0f / ssum;
#pragma unroll
      for (int t2 = 0; t2 < 6; t2++) p[t2] = sc[t2] * inv;
      stageT2(wt2, wv + l * 4624, 68, 68, tid);
    }
    __syncthreads();

    // V = Wv*H -> A (Q dead)
    gemm(wt2, Hs, As, 68, 68, nullptr, false, tr, col0);
    __syncthreads();

    // Attn = p * V -> B (K dead); also stage proj
#pragma unroll 1
    for (int dd = 0; dd < 34; dd++) {
      float acc = 0.f;
#pragma unroll
      for (int t2 = 0; t2 < 6; t2++)
        acc = fmaf(p[t2], As[(hd * 34 + dd) * 96 + s * 6 + t2], acc);
      Bs[(hd * 34 + dd) * 96 + c] = acc;
    }
    stageT2(wt2, projw + l * 4624, 68, 68, tid);
    __syncthreads();

    // P = proj*Attn + b -> A
    gemm(wt2, Bs, As, 68, 68, projb + l * 68, false, tr, col0);
    __syncthreads();

    // LN1: H = LN(H + P); also stage ff1
    if (tid < 96) {
      float h[68];
      float m = 0.f;
#pragma unroll
      for (int e = 0; e < 68; e++) { h[e] = Hs[e * 96 + c] + As[e * 96 + c]; m += h[e]; }
      m *= (1.0f / 68.0f);
      float v = 0.f;
#pragma unroll
      for (int e = 0; e < 68; e++) { float d = h[e] - m; v = fmaf(d, d, v); }
      float rr = rsqrtf(v * (1.0f / 68.0f) + 1e-5f);
#pragma unroll
      for (int e = 0; e < 68; e++)
        Hs[e * 96 + c] = fmaf((h[e] - m) * rr, __ldg(ln1g + l * 68 + e), __ldg(ln1b + l * 68 + e));
    }
    stageT2(wt2, ff1w + l * 2312, 34, 68, tid);
    __syncthreads();

    // F = relu(ff1*H + b) -> A (34 rows)
    gemm(wt2, Hs, As, 68, 34, ff1b + l * 34, true, tr, col0);
    __syncthreads();
    stageT2(wt2, ff2w + l * 2312, 68, 34, tid);
    __syncthreads();

    // G = ff2*F + b -> B
    gemm(wt2, As, Bs, 34, 68, ff2b + l * 68, false, tr, col0);
    __syncthreads();

    // LN2 (+final LN): H = LN(H + G)
    if (tid < 96) {
      float h[68];
      float m = 0.f;
#pragma unroll
      for (int e = 0; e < 68; e++) { h[e] = Hs[e * 96 + c] + Bs[e * 96 + c]; m += h[e]; }
      m *= (1.0f / 68.0f);
      float v = 0.f;
#pragma unroll
      for (int e = 0; e < 68; e++) { float d = h[e] - m; v = fmaf(d, d, v); }
      float rr = rsqrtf(v * (1.0f / 68.0f) + 1e-5f);
#pragma unroll
      for (int e = 0; e < 68; e++)
        h[e] = fmaf((h[e] - m) * rr, __ldg(ln2g + l * 68 + e), __ldg(ln2b + l * 68 + e));
      if (l == 1) {
        m = 0.f;
#pragma unroll
        for (int e = 0; e < 68; e++) m += h[e];
        m *= (1.0f / 68.0f);
        v = 0.f;
#pragma unroll
        for (int e = 0; e < 68; e++) { float d = h[e] - m; v = fmaf(d, d, v); }
        rr = rsqrtf(v * (1.0f / 68.0f) + 1e-5f);
#pragma unroll
        for (int e = 0; e < 68; e++)
          h[e] = fmaf((h[e] - m) * rr, __ldg(lnfg + e), __ldg(lnfb + e));
      }
#pragma unroll
      for (int e = 0; e < 68; e++) Hs[e * 96 + c] = h[e];
    }
  }

  // final FC [6 x 408]; fcw staged into WT region (floats)
  __syncthreads();
#pragma unroll 1
  for (int idx = tid; idx < 2448; idx += TPB) smf[WT2_U + idx] = __ldg(fcw + idx);
  __syncthreads();
  if (tid < 96) {
    float h[68];
#pragma unroll
    for (int e = 0; e < 68; e++) h[e] = Hs[e * 96 + c];
#pragma unroll 1
    for (int o = 0; o < 6; o++) {
      const float* wrow = smf + WT2_U + o * 408 + t * 68;
      float acc = 0.f;
#pragma unroll
      for (int e = 0; e < 68; e++) acc = fmaf(h[e], wrow[e], acc);
      smf[RED_F + s * 36 + t * 6 + o] = acc;
    }
  }
  __syncthreads();
  if (tid < SPB) {
    int ss = tid;
#pragma unroll 1
    for (int o = 0; o < 6; o++) {
      float v = __ldg(fcb + o);
#pragma unroll
      for (int tt = 0; tt < 6; tt++) v += smf[RED_F + ss * 36 + tt * 6 + o];
      out[(size_t)(samp0 + ss) * 6 + o] = fmaxf(v, 0.f);
    }
  }
}

extern "C" void kernel_launch(void* const* d_in, const int* in_sizes, int n_in,
                              void* d_out, int out_size) {
  const float* x     = (const float*)d_in[0];
  const float* convw = (const float*)d_in[1];
  const float* convb = (const float*)d_in[2];
  const float* lembw = (const float*)d_in[3];
  const float* lembb = (const float*)d_in[4];
  const float* wq    = (const float*)d_in[5];
  const float* wk    = (const float*)d_in[6];
  const float* wv    = (const float*)d_in[7];
  const float* projw = (const float*)d_in[8];
  const float* projb = (const float*)d_in[9];
  const float* ff1w  = (const float*)d_in[10];
  const float* ff1b  = (const float*)d_in[11];
  const float* ff2w  = (const float*)d_in[12];
  const float* ff2b  = (const float*)d_in[13];
  const float* ln1g  = (const float*)d_in[14];
  const float* ln1b  = (const float*)d_in[15];
  const float* ln2g  = (const float*)d_in[16];
  const float* ln2b  = (const float*)d_in[17];
  const float* lnfg  = (const float*)d_in[18];
  const float* lnfb  = (const float*)d_in[19];
  const float* fcw   = (const float*)d_in[20];
  const float* fcb   = (const float*)d_in[21];
  float* out = (float*)d_out;

  int B = in_sizes[0] / (6 * 37 * 5);   // 32768
  int grid = B / SPB;                   // 2048
  int smem = SM_FLOATS * 4;             // 101,040 B

  static int configured = 0;
  if (!configured) {
    cudaFuncSetAttribute(dan_kernel, cudaFuncAttributeMaxDynamicSharedMemorySize, smem);
    configured = 1;
  }
  dan_kernel<<<grid, TPB, smem>>>(
      x, convw, convb, lembw, lembb, wq, wk, wv, projw, projb,
      ff1w, ff1b, ff2w, ff2b, ln1g, ln1b, ln2g, ln2b, lnfg, lnfb,
      fcw, fcb, out);
}

// round 9
// speedup vs baseline: 2.5464x; 1.1199x over previous
#include <cuda_runtime.h>

// DeepArcNet v5: block GEMM (16 samples / 96 cols, TPB=192) with split-K
// double-buffered weight staging pipelined through the GEMMs:
// each phase = [LDG next weight half] [gemm current half] [STS next half] [bar],
// hiding global-load latency behind compute. Accumulators persist across halves.

#define TPB 192
#define SPB 16

typedef unsigned long long ull;

// float-offset layout in dynamic shared (101,040 B total)
#define WT_U  0                    // ull wt[2][34*37] = 20128 B; floats alias for fc
#define H_F   5032                 // H  [68][96]
#define A_F   (H_F + 6528)         // A  [68][96] (aliased: conv scratch 16*102)
#define B_F   (A_F + 6528)         // B  [68][96]
#define POS_F (B_F + 6528)         // pos[68]
#define RED_F (POS_F + 68)         // red[16][36]
#define SM_FLOATS (RED_F + 576)

#define WHALF 1258                 // ull per wt half-buffer (34*37)

__device__ __forceinline__ ull pk2(float x, float y) {
  ull r; asm("mov.b64 %0, {%1,%2};" : "=l"(r) : "f"(x), "f"(y)); return r;
}
__device__ __forceinline__ void upk2(ull a, float& x, float& y) {
  asm("mov.b64 {%0,%1}, %2;" : "=f"(x), "=f"(y) : "l"(a));
}
__device__ __forceinline__ ull ffma2(ull a, ull b, ull c) {
  ull d; asm("fma.rn.f32x2 %0, %1, %2, %3;" : "=l"(d) : "l"(a), "l"(b), "l"(c)); return d;
}

// ---- pipelined weight staging (34 k-rows, NP row-pairs) ----
// src points at W + h*34 within a row-major [NR][Krow] matrix.
struct StReg { float x[7], y[7]; };

__device__ __forceinline__ void stage_ld(StReg& r, const float* __restrict__ src,
                                         int NP, int Krow, int tid) {
  int n = 34 * NP;
#pragma unroll
  for (int i = 0; i < 7; i++) {
    int idx = tid + i * TPB;
    if (idx < n) {
      int p = idx / 34, e = idx - p * 34;
      const float* sp = src + (2 * p) * Krow + e;
      r.x[i] = __ldg(sp); r.y[i] = __ldg(sp + Krow);
    }
  }
}
__device__ __forceinline__ void stage_st(const StReg& r, ull* wt, int NP, int tid) {
  int n = 34 * NP;
#pragma unroll
  for (int i = 0; i < 7; i++) {
    int idx = tid + i * TPB;
    if (idx < n) {
      int p = idx / 34, e = idx - p * 34;
      wt[e * 37 + p] = pk2(r.x[i], r.y[i]);
    }
  }
}

// ---- 34-k gemm accumulate: acc[rp][cc] += W-pairs * act  ----
// hp = activation base + halfrow*96 + col0
__device__ __forceinline__ void gemm34(ull* acc, const ull* wt, const float* hp, int tr) {
  const ull* wp = wt + tr * 6;
#pragma unroll 2
  for (int e = 0; e < 34; e++) {
    ull wv[6];
#pragma unroll
    for (int rp = 0; rp < 6; rp++) wv[rp] = wp[e * 37 + rp];
    ull hv[3];
#pragma unroll
    for (int cc = 0; cc < 3; cc++) { float h = hp[e * 96 + cc]; hv[cc] = pk2(h, h); }
#pragma unroll
    for (int rp = 0; rp < 6; rp++)
#pragma unroll
      for (int cc = 0; cc < 3; cc++)
        acc[rp * 3 + cc] = ffma2(wv[rp], hv[cc], acc[rp * 3 + cc]);
  }
}
__device__ __forceinline__ void acczero(ull* acc) {
#pragma unroll
  for (int i = 0; i < 18; i++) acc[i] = 0ull;
}
__device__ __forceinline__ void accstore(const ull* acc, float* dst, int NR,
                                         const float* __restrict__ bias, bool relu,
                                         int tr, int col0) {
#pragma unroll
  for (int rp = 0; rp < 6; rp++) {
    int d0 = tr * 12 + rp * 2;
    if (d0 < NR) {
      float b0 = bias ? __ldg(bias + d0) : 0.f;
      float b1 = bias ? __ldg(bias + d0 + 1) : 0.f;
#pragma unroll
      for (int cc = 0; cc < 3; cc++) {
        float f0, f1; upk2(acc[rp * 3 + cc], f0, f1);
        f0 += b0; f1 += b1;
        if (relu) { f0 = fmaxf(f0, 0.f); f1 = fmaxf(f1, 0.f); }
        dst[d0 * 96 + col0 + cc] = f0;
        dst[(d0 + 1) * 96 + col0 + cc] = f1;
      }
    }
  }
}

__global__ void __launch_bounds__(TPB) dan_kernel(
    const float* __restrict__ x,     const float* __restrict__ convw,
    const float* __restrict__ convb, const float* __restrict__ lembw,
    const float* __restrict__ lembb, const float* __restrict__ wq,
    const float* __restrict__ wk,    const float* __restrict__ wv,
    const float* __restrict__ projw, const float* __restrict__ projb,
    const float* __restrict__ ff1w,  const float* __restrict__ ff1b,
    const float* __restrict__ ff2w,  const float* __restrict__ ff2b,
    const float* __restrict__ ln1g,  const float* __restrict__ ln1b,
    const float* __restrict__ ln2g,  const float* __restrict__ ln2b,
    const float* __restrict__ lnfg,  const float* __restrict__ lnfb,
    const float* __restrict__ fcw,   const float* __restrict__ fcb,
    float* __restrict__ out)
{
  extern __shared__ float smf[];
  ull* w0 = reinterpret_cast<ull*>(smf);
  ull* w1 = w0 + WHALF;
  float* Hs = smf + H_F;
  float* As = smf + A_F;
  float* Bs = smf + B_F;
  const int tid = threadIdx.x;
  const int samp0 = blockIdx.x * SPB;
  const int tr = tid >> 5, col0 = (tid & 31) * 3;
  const int g = tid / 96, c = tid - g * 96;    // head-group, column
  const int s = c / 6, t = c - s * 6;

  // pos table
  if (tid < 68) {
    int tt = tid >> 2, j4 = tid & 3;
    float ang = (j4 & 1) ? ((float)tt * (1.0f / 18.0f)) : (float)tt;
    smf[POS_F + tid] = (j4 < 2) ? sinf(ang) : cosf(ang);
  }

  // conv -> scratch (aliases A)
#pragma unroll 1
  for (int o = tid; o < SPB * 102; o += TPB) {
    int ss = o / 102, r = o % 102, ch = r / 17, tt = r % 17;
    const float* xp = x + ((size_t)(samp0 + ss) * 6 + ch) * 185 + tt * 10;
    float acc = 0.f;
#pragma unroll
    for (int i = 0; i < 25; i++) acc = fmaf(__ldg(xp + i), __ldg(convw + ch * 25 + i), acc);
    As[ss * 102 + ch * 17 + tt] = fmaxf(acc + __ldg(convb + ch), 0.f);
  }
  __syncthreads();

  // embed -> H, overlapped with stage(Q0 layer0 -> w0)
  {
    StReg r; stage_ld(r, wq, 34, 68, tid);
    if (tid < 96) {
      float lw[4], lb[4];
#pragma unroll
      for (int q4 = 0; q4 < 4; q4++) {
        lw[q4] = __ldg(lembw + t * 4 + q4);
        lb[q4] = __ldg(lembb + t * 4 + q4);
      }
#pragma unroll 1
      for (int tt = 0; tt < 17; tt++) {
        float xv = As[s * 102 + t * 17 + tt];
#pragma unroll
        for (int q4 = 0; q4 < 4; q4++) {
          int e = tt * 4 + q4;
          Hs[e * 96 + c] = fmaf(xv, lw[q4], lb[q4]) + smf[POS_F + e];
        }
      }
    }
    stage_st(r, w0, 34, tid);
  }
  __syncthreads();

  float p[6];   // softmax probs (head g, column c)
  ull acc[18];

#pragma unroll 1
  for (int l = 0; l < 2; l++) {
    const float* wql = wq + l * 4624;
    const float* wkl = wk + l * 4624;
    const float* wvl = wv + l * 4624;
    const float* pwl = projw + l * 4624;
    const float* f1l = ff1w + l * 2312;
    const float* f2l = ff2w + l * 2312;

    // ph1: gemmQ(h0); stage Q1->w1
    acczero(acc);
    { StReg r; stage_ld(r, wql + 34, 34, 68, tid);
      gemm34(acc, w0, Hs + col0, tr);
      stage_st(r, w1, 34, tid); }
    __syncthreads();
    // ph2: gemmQ(h1)->A; stage K0->w0
    { StReg r; stage_ld(r, wkl, 34, 68, tid);
      gemm34(acc, w1, Hs + 34 * 96 + col0, tr);
      accstore(acc, As, 68, nullptr, false, tr, col0);
      stage_st(r, w0, 34, tid); }
    __syncthreads();
    // ph3: gemmK(h0); stage K1->w1
    acczero(acc);
    { StReg r; stage_ld(r, wkl + 34, 34, 68, tid);
      gemm34(acc, w0, Hs + col0, tr);
      stage_st(r, w1, 34, tid); }
    __syncthreads();
    // ph4: gemmK(h1)->B; stage V0->w0
    { StReg r; stage_ld(r, wvl, 34, 68, tid);
      gemm34(acc, w1, Hs + 34 * 96 + col0, tr);
      accstore(acc, Bs, 68, nullptr, false, tr, col0);
      stage_st(r, w0, 34, tid); }
    __syncthreads();
    // ph5: scores+softmax (A=Q, B=K -> p); gemmV(h0); stage V1->w1
    {
      StReg r; stage_ld(r, wvl + 34, 34, 68, tid);
      {
        float qv[34];
#pragma unroll 1
        for (int d = 0; d < 34; d++) qv[d] = As[(g * 34 + d) * 96 + c];
        float sc[6];
#pragma unroll 1
        for (int t2 = 0; t2 < 6; t2++) {
          float a2 = 0.f;
#pragma unroll
          for (int d = 0; d < 34; d++)
            a2 = fmaf(qv[d], Bs[(g * 34 + d) * 96 + s * 6 + t2], a2);
          sc[t2] = a2 * 0.17149858514f;  // 34^-0.5
        }
        float mx = sc[0];
#pragma unroll
        for (int t2 = 1; t2 < 6; t2++) mx = fmaxf(mx, sc[t2]);
        float ssum = 0.f;
#pragma unroll
        for (int t2 = 0; t2 < 6; t2++) { sc[t2] = __expf(sc[t2] - mx); ssum += sc[t2]; }
        float inv = 1.0f / ssum;
#pragma unroll
        for (int t2 = 0; t2 < 6; t2++) p[t2] = sc[t2] * inv;
      }
      acczero(acc);
      gemm34(acc, w0, Hs + col0, tr);
      stage_st(r, w1, 34, tid);
    }
    __syncthreads();
    // ph6: gemmV(h1)->A (Q dead); stage P0->w0
    { StReg r; stage_ld(r, pwl, 34, 68, tid);
      gemm34(acc, w1, Hs + 34 * 96 + col0, tr);
      accstore(acc, As, 68, nullptr, false, tr, col0);
      stage_st(r, w0, 34, tid); }
    __syncthreads();
    // ph7: attnV: B[g*34+dd][c] = sum_t2 p[t2]*A[g*34+dd][s6+t2]; stage P1->w1
    { StReg r; stage_ld(r, pwl + 34, 34, 68, tid);
#pragma unroll 1
      for (int dd = 0; dd < 34; dd++) {
        float a2 = 0.f;
#pragma unroll
        for (int t2 = 0; t2 < 6; t2++)
          a2 = fmaf(p[t2], As[(g * 34 + dd) * 96 + s * 6 + t2], a2);
        Bs[(g * 34 + dd) * 96 + c] = a2;
      }
      stage_st(r, w1, 34, tid); }
    __syncthreads();
    // ph8: gemmP(h0) over B
    acczero(acc);
    gemm34(acc, w0, Bs + col0, tr);
    __syncthreads();
    // ph9: gemmP(h1)->A (+bias) (V dead); stage F1_0->w0
    { StReg r; stage_ld(r, f1l, 17, 68, tid);
      gemm34(acc, w1, Bs + 34 * 96 + col0, tr);
      accstore(acc, As, 68, projb + l * 68, false, tr, col0);
      stage_st(r, w0, 17, tid); }
    __syncthreads();
    // ph10: LN1 H = LN(H+A); stage F1_1->w1
    { StReg r; stage_ld(r, f1l + 34, 17, 68, tid);
      if (tid < 96) {
        float h[68]; float m = 0.f;
#pragma unroll
        for (int e = 0; e < 68; e++) { h[e] = Hs[e * 96 + c] + As[e * 96 + c]; m += h[e]; }
        m *= (1.0f / 68.0f);
        float v = 0.f;
#pragma unroll
        for (int e = 0; e < 68; e++) { float d = h[e] - m; v = fmaf(d, d, v); }
        float rr = rsqrtf(v * (1.0f / 68.0f) + 1e-5f);
#pragma unroll
        for (int e = 0; e < 68; e++)
          Hs[e * 96 + c] = fmaf((h[e] - m) * rr, __ldg(ln1g + l * 68 + e), __ldg(ln1b + l * 68 + e));
      }
      stage_st(r, w1, 17, tid); }
    __syncthreads();
    // ph11: gemmF1(h0)
    acczero(acc);
    gemm34(acc, w0, Hs + col0, tr);
    __syncthreads();
    // ph12: gemmF1(h1)->B rows 0..33 (+bias, relu); stage F2(full K=34)->w0
    { StReg r; stage_ld(r, f2l, 34, 34, tid);
      gemm34(acc, w1, Hs + 34 * 96 + col0, tr);
      accstore(acc, Bs, 34, ff1b + l * 34, true, tr, col0);
      stage_st(r, w0, 34, tid); }
    __syncthreads();
    // ph13: gemmF2 (K=34) -> A (+bias) (P dead)
    acczero(acc);
    gemm34(acc, w0, Bs + col0, tr);
    accstore(acc, As, 68, ff2b + l * 68, false, tr, col0);
    __syncthreads();
    // ph14: LN2 (+final LN); stage next (Q0 layer1 or fcw floats) -> w0
    if (tid < 96) {
      float h[68]; float m = 0.f;
#pragma unroll
      for (int e = 0; e < 68; e++) { h[e] = Hs[e * 96 + c] + As[e * 96 + c]; m += h[e]; }
      m *= (1.0f / 68.0f);
      float v = 0.f;
#pragma unroll
      for (int e = 0; e < 68; e++) { float d = h[e] - m; v = fmaf(d, d, v); }
      float rr = rsqrtf(v * (1.0f / 68.0f) + 1e-5f);
#pragma unroll
      for (int e = 0; e < 68; e++)
        h[e] = fmaf((h[e] - m) * rr, __ldg(ln2g + l * 68 + e), __ldg(ln2b + l * 68 + e));
      if (l == 1) {
        m = 0.f;
#pragma unroll
        for (int e = 0; e < 68; e++) m += h[e];
        m *= (1.0f / 68.0f);
        v = 0.f;
#pragma unroll
        for (int e = 0; e < 68; e++) { float d = h[e] - m; v = fmaf(d, d, v); }
        rr = rsqrtf(v * (1.0f / 68.0f) + 1e-5f);
#pragma unroll
        for (int e = 0; e < 68; e++)
          h[e] = fmaf((h[e] - m) * rr, __ldg(lnfg + e), __ldg(lnfb + e));
      }
#pragma unroll
      for (int e = 0; e < 68; e++) Hs[e * 96 + c] = h[e];
    }
    if (l == 0) {
      StReg r; stage_ld(r, wq + 4624, 34, 68, tid);
      stage_st(r, w0, 34, tid);
    } else {
#pragma unroll 1
      for (int idx = tid; idx < 2448; idx += TPB) smf[WT_U + idx] = __ldg(fcw + idx);
    }
    __syncthreads();
  }

  // final FC [6 x 408] from wt floats
  if (tid < 96) {
    float h[68];
#pragma unroll
    for (int e = 0; e < 68; e++) h[e] = Hs[e * 96 + c];
#pragma unroll 1
    for (int o = 0; o < 6; o++) {
      const float* wrow = smf + WT_U + o * 408 + t * 68;
      float a2 = 0.f;
#pragma unroll
      for (int e = 0; e < 68; e++) a2 = fmaf(h[e], wrow[e], a2);
      smf[RED_F + s * 36 + t * 6 + o] = a2;
    }
  }
  __syncthreads();
  if (tid < SPB) {
    int ss = tid;
#pragma unroll 1
    for (int o = 0; o < 6; o++) {
      float v = __ldg(fcb + o);
#pragma unroll
      for (int tt = 0; tt < 6; tt++) v += smf[RED_F + ss * 36 + tt * 6 + o];
      out[(size_t)(samp0 + ss) * 6 + o] = fmaxf(v, 0.f);
    }
  }
}

extern "C" void kernel_launch(void* const* d_in, const int* in_sizes, int n_in,
                              void* d_out, int out_size) {
  const float* x     = (const float*)d_in[0];
  const float* convw = (const float*)d_in[1];
  const float* convb = (const float*)d_in[2];
  const float* lembw = (const float*)d_in[3];
  const float* lembb = (const float*)d_in[4];
  const float* wq    = (const float*)d_in[5];
  const float* wk    = (const float*)d_in[6];
  const float* wv    = (const float*)d_in[7];
  const float* projw = (const float*)d_in[8];
  const float* projb = (const float*)d_in[9];
  const float* ff1w  = (const float*)d_in[10];
  const float* ff1b  = (const float*)d_in[11];
  const float* ff2w  = (const float*)d_in[12];
  const float* ff2b  = (const float*)d_in[13];
  const float* ln1g  = (const float*)d_in[14];
  const float* ln1b  = (const float*)d_in[15];
  const float* ln2g  = (const float*)d_in[16];
  const float* ln2b  = (const float*)d_in[17];
  const float* lnfg  = (const float*)d_in[18];
  const float* lnfb  = (const float*)d_in[19];
  const float* fcw   = (const float*)d_in[20];
  const float* fcb   = (const float*)d_in[21];
  float* out = (float*)d_out;

  int B = in_sizes[0] / (6 * 37 * 5);   // 32768
  int grid = B / SPB;                   // 2048
  int smem = SM_FLOATS * 4;             // 101,040 B

  static int configured = 0;
  if (!configured) {
    cudaFuncSetAttribute(dan_kernel, cudaFuncAttributeMaxDynamicSharedMemorySize, smem);
    configured = 1;
  }
  dan_kernel<<<grid, TPB, smem>>>(
      x, convw, convb, lembw, lembb, wq, wk, wv, projw, projb,
      ff1w, ff1b, ff2w, ff2b, ln1g, ln1b, ln2g, ln2b, lnfg, lnfb,
      fcw, fcb, out);
}